// round 6
// baseline (speedup 1.0000x reference)
#include <cuda_runtime.h>
#include <cuda_fp16.h>
#include <cstdint>

// out[i,j,k] = sum_d x[i+1,d]*x[j+1,d]*Wp[d,k] + b[k]
// (diff_term antisymmetric -> cancels under (i,j) symmetrization; prod_term symmetric)
//
// fp16 asymmetric split (Zh + Zl*4096 vs single-fp16 X) on legacy mma.sync.
// Split-K=3 (chunks 7/7/6 of K64) -> 408 CTAs = one wave at occupancy 3.
// Partial fragment quads -> scratch -> reduce kernel (sum splits + bias + dual writeout).

#define OUTN 510
#define DDIM 1280
#define NTB 16
#define NTRI 136
#define KC 64
#define NCH 20
#define SPLITS 3
#define CPS 7              // max chunks per split
#define STAGES 3
#define STAGE_BYTES 20480   // Ahi 8K | Alo 8K | Bhi 4K
#define SA_HI 0
#define SA_LO 8192
#define SB_HI 16384
#define SMEM_REQ (STAGES * STAGE_BYTES + 128)

__device__ __align__(128) __half g_Xh[512 * DDIM];
__device__ __align__(128) __half g_Zh[2][512 * DDIM];
__device__ __align__(128) __half g_Zl[2][512 * DDIM];
__device__ __align__(128) float g_part[(size_t)SPLITS * NTRI * 2048];

// ---------------- helpers ----------------
__device__ __forceinline__ uint32_t smem_u32(const void* p) {
    uint32_t a;
    asm("{ .reg .u64 t; cvta.to.shared.u64 t, %1; cvt.u32.u64 %0, t; }" : "=r"(a) : "l"(p));
    return a;
}
__device__ __forceinline__ uint32_t pk2h(float a, float b) {
    __half2 t = __floats2half2_rn(a, b);
    return *reinterpret_cast<uint32_t*>(&t);
}
__device__ __forceinline__ float h16(float v) {
    return __half2float(__float2half_rn(v));
}

#define CPA(dst, src) \
    asm volatile("cp.async.cg.shared.global [%0], [%1], 16;" :: "r"(dst), "l"(src))
#define CP_COMMIT() asm volatile("cp.async.commit_group;" ::: "memory")
#define CP_WAIT1()  asm volatile("cp.async.wait_group 1;" ::: "memory")

#define LDSM4(r0, r1, r2, r3, addr) \
    asm volatile("ldmatrix.sync.aligned.m8n8.x4.shared.b16 {%0,%1,%2,%3}, [%4];" \
                 : "=r"(r0), "=r"(r1), "=r"(r2), "=r"(r3) : "r"(addr))

#define MMA16816(d, a, b0, b1) \
    asm volatile("mma.sync.aligned.m16n8k16.row.col.f32.f16.f16.f32 " \
                 "{%0,%1,%2,%3}, {%4,%5,%6,%7}, {%8,%9}, {%0,%1,%2,%3};" \
                 : "+f"(d[0]), "+f"(d[1]), "+f"(d[2]), "+f"(d[3]) \
                 : "r"(a[0]), "r"(a[1]), "r"(a[2]), "r"(a[3]), "r"(b0), "r"(b1))

// ---------------- prep: fp32 -> fp16 planes ----------------
__global__ __launch_bounds__(256, 4)
void prep_kernel(const float* __restrict__ x, const float* __restrict__ W) {
    int idx = blockIdx.x * 256 + threadIdx.x;   // < 512*320
    int r = idx / 320;
    int d0 = (idx - r * 320) * 4;
    size_t p = (size_t)r * DDIM + d0;

    float4 xv = *(const float4*)&x[p];
    float4 wA = *(const float4*)&W[2 * d0];      // (w0,w1) for d0, d0+1
    float4 wB = *(const float4*)&W[2 * d0 + 4];  // d0+2, d0+3

    *(uint2*)&g_Xh[p] = make_uint2(pk2h(xv.x, xv.y), pk2h(xv.z, xv.w));

    float z0 = xv.x * wA.x, z1 = xv.y * wA.z, z2 = xv.z * wB.x, z3 = xv.w * wB.z;
    float h0 = h16(z0), h1 = h16(z1), h2 = h16(z2), h3 = h16(z3);
    *(uint2*)&g_Zh[0][p] = make_uint2(pk2h(z0, z1), pk2h(z2, z3));
    *(uint2*)&g_Zl[0][p] = make_uint2(pk2h((z0 - h0) * 4096.f, (z1 - h1) * 4096.f),
                                      pk2h((z2 - h2) * 4096.f, (z3 - h3) * 4096.f));

    z0 = xv.x * wA.y; z1 = xv.y * wA.w; z2 = xv.z * wB.y; z3 = xv.w * wB.w;
    h0 = h16(z0); h1 = h16(z1); h2 = h16(z2); h3 = h16(z3);
    *(uint2*)&g_Zh[1][p] = make_uint2(pk2h(z0, z1), pk2h(z2, z3));
    *(uint2*)&g_Zl[1][p] = make_uint2(pk2h((z0 - h0) * 4096.f, (z1 - h1) * 4096.f),
                                      pk2h((z2 - h2) * 4096.f, (z3 - h3) * 4096.f));
}

// ---------------- GEMM (split-K partial): D[64(mk),32(n)] ----------------
__global__ __launch_bounds__(256, 3)
void pcm_mma_kernel() {
    extern __shared__ char smraw[];
    uint32_t sb = smem_u32(smraw);
    uint32_t base = (sb + 127) & ~127u;

    // triangular tile decode
    int t = blockIdx.x, ti = 0;
    while (t >= NTB - ti) { t -= NTB - ti; ++ti; }
    int tj = ti + t;
    const int i0 = ti * 32, j0 = tj * 32;
    const int split = blockIdx.y;
    const int c0 = split * CPS;
    const int c1 = (split == SPLITS - 1) ? NCH : c0 + CPS;

    const int tid = threadIdx.x;
    const int wid = tid >> 5, L = tid & 31;

    // ---- copy lanes: row = tid>>3 (0..31), 16B col group = tid&7
    const int arow = tid >> 3;
    const int cg = tid & 7;
    int ri = i0 + arow + 1; if (ri > 511) ri = 511;
    int rj = j0 + arow + 1; if (rj > 511) rj = 511;
    const __half* sAh0 = &g_Zh[0][(size_t)ri * DDIM + cg * 8];
    const __half* sAh1 = &g_Zh[1][(size_t)ri * DDIM + cg * 8];
    const __half* sAl0 = &g_Zl[0][(size_t)ri * DDIM + cg * 8];
    const __half* sAl1 = &g_Zl[1][(size_t)ri * DDIM + cg * 8];
    const __half* sBh  = &g_Xh[(size_t)rj * DDIM + cg * 8];
    const uint32_t swc = (uint32_t)((cg * 16) ^ ((arow & 7) * 16));
    const uint32_t dA0  = SA_HI + arow * 128 + swc;
    const uint32_t dA1  = SA_HI + (arow + 32) * 128 + swc;
    const uint32_t dAl0 = SA_LO + arow * 128 + swc;
    const uint32_t dAl1 = SA_LO + (arow + 32) * 128 + swc;
    const uint32_t dB   = SB_HI + arow * 128 + swc;

    // prologue: chunks c0, c0+1
#pragma unroll
    for (int p = 0; p < STAGES - 1; p++) {
        const int c = c0 + p;
        uint32_t st = base + (c % STAGES) * STAGE_BYTES;
        size_t off = (size_t)c * KC;
        CPA(st + dA0, sAh0 + off);  CPA(st + dA1, sAh1 + off);
        CPA(st + dAl0, sAl0 + off); CPA(st + dAl1, sAl1 + off);
        CPA(st + dB, sBh + off);
        CP_COMMIT();
    }

    // ---- mma fragment addressing (per lane, swizzle-resolved)
    const int warpM = wid >> 1;        // 0..3 -> A rows 16*warpM
    const int warpN = wid & 1;         // 0..1 -> B rows 16*warpN
    const int a_r = warpM * 16 + (L & 7) + ((L >> 3) & 1) * 8;   // 0..63
    const uint32_t a_cb0 = ((L >> 4) & 1) * 16;
    const uint32_t a_xm = (a_r & 7) * 16;
    const uint32_t aRow = SA_HI + a_r * 128;
    const int b_r = warpN * 16 + (L & 7) + ((L >> 4) & 1) * 8;   // 0..31
    const uint32_t b_cb0 = ((L >> 3) & 1) * 16;
    const uint32_t b_xm = (b_r & 7) * 16;
    const uint32_t bRow = SB_HI + b_r * 128;

    float acc0H[4] = {0.f, 0.f, 0.f, 0.f};
    float acc1H[4] = {0.f, 0.f, 0.f, 0.f};
    float acc0L[4] = {0.f, 0.f, 0.f, 0.f};
    float acc1L[4] = {0.f, 0.f, 0.f, 0.f};

    for (int c = c0; c < c1; c++) {
        CP_WAIT1();
        __syncthreads();      // chunk c resident; all warps done with older stage

        if (c + STAGES - 1 < c1) {
            const int cn = c + STAGES - 1;
            uint32_t st = base + (cn % STAGES) * STAGE_BYTES;
            size_t off = (size_t)cn * KC;
            CPA(st + dA0, sAh0 + off);  CPA(st + dA1, sAh1 + off);
            CPA(st + dAl0, sAl0 + off); CPA(st + dAl1, sAl1 + off);
            CPA(st + dB, sBh + off);
        }
        CP_COMMIT();

        const uint32_t stg = base + (c % STAGES) * STAGE_BYTES;
#pragma unroll
        for (int kk = 0; kk < 4; kk++) {
            uint32_t ah[4], al[4], bh[4];
            const uint32_t aAddr = stg + aRow + ((a_cb0 + kk * 32) ^ a_xm);
            const uint32_t bAddr = stg + bRow + ((b_cb0 + kk * 32) ^ b_xm);
            LDSM4(ah[0], ah[1], ah[2], ah[3], aAddr);
            LDSM4(al[0], al[1], al[2], al[3], aAddr + (SA_LO - SA_HI));
            LDSM4(bh[0], bh[1], bh[2], bh[3], bAddr);
            MMA16816(acc0H, ah, bh[0], bh[1]);  MMA16816(acc1H, ah, bh[2], bh[3]);
            MMA16816(acc0L, al, bh[0], bh[1]);  MMA16816(acc1L, al, bh[2], bh[3]);
        }
    }

    // ---- epilogue: combine hi/lo, dump fragment quads to scratch (coalesced)
    const float s = 1.f / 4096.f;
    float4* dst = (float4*)&g_part[(((size_t)split * NTRI + blockIdx.x) * 2048)];
    dst[tid]       = make_float4(acc0H[0] + s * acc0L[0], acc0H[1] + s * acc0L[1],
                                 acc0H[2] + s * acc0L[2], acc0H[3] + s * acc0L[3]);
    dst[256 + tid] = make_float4(acc1H[0] + s * acc1L[0], acc1H[1] + s * acc1L[1],
                                 acc1H[2] + s * acc1L[2], acc1H[3] + s * acc1L[3]);
}

// ---------------- reduce: sum splits, add bias, dual-orientation writeout ----------------
__global__ __launch_bounds__(256, 4)
void pcm_reduce_kernel(float* __restrict__ out, const float* __restrict__ bias) {
    __shared__ float Ds[64 * 33];

    int t = blockIdx.x, ti = 0;
    while (t >= NTB - ti) { t -= NTB - ti; ++ti; }
    int tj = ti + t;
    const int i0 = ti * 32, j0 = tj * 32;

    const int tid = threadIdx.x;
    const int wid = tid >> 5, L = tid & 31;
    const int warpM = wid >> 1, warpN = wid & 1;

    float4 q0 = make_float4(0.f, 0.f, 0.f, 0.f);
    float4 q1 = make_float4(0.f, 0.f, 0.f, 0.f);
#pragma unroll
    for (int sp = 0; sp < SPLITS; sp++) {
        const float4* src = (const float4*)&g_part[(((size_t)sp * NTRI + blockIdx.x) * 2048)];
        float4 v = src[tid];
        q0.x += v.x; q0.y += v.y; q0.z += v.z; q0.w += v.w;
        v = src[256 + tid];
        q1.x += v.x; q1.y += v.y; q1.z += v.z; q1.w += v.w;
    }

    const int dr = warpM * 16 + (L >> 2);
    const int dc = warpN * 16 + (L & 3) * 2;
    Ds[dr * 33 + dc]           = q0.x;
    Ds[dr * 33 + dc + 1]       = q0.y;
    Ds[(dr + 8) * 33 + dc]     = q0.z;
    Ds[(dr + 8) * 33 + dc + 1] = q0.w;
    Ds[dr * 33 + dc + 8]       = q1.x;
    Ds[dr * 33 + dc + 9]       = q1.y;
    Ds[(dr + 8) * 33 + dc + 8] = q1.z;
    Ds[(dr + 8) * 33 + dc + 9] = q1.w;
    __syncthreads();

    const float b0 = bias[0], b1 = bias[1];

    // main orientation: out[i][j][k], float4 = (j,k0),(j,k1),(j+1,k0),(j+1,k1)
#pragma unroll
    for (int p = 0; p < 2; p++) {
        int task = tid + p * 256;
        int r = task & 31, cp = task >> 5;     // r: i-row, cp: j-pair
        int i = i0 + r, j = j0 + 2 * cp;
        if (i < OUTN && j < OUTN - 1) {
            float4 v = make_float4(Ds[r * 33 + 2 * cp] + b0,
                                   Ds[(r + 32) * 33 + 2 * cp] + b1,
                                   Ds[r * 33 + 2 * cp + 1] + b0,
                                   Ds[(r + 32) * 33 + 2 * cp + 1] + b1);
            *(float4*)&out[((size_t)i * OUTN + j) * 2] = v;
        }
    }

    // mirror orientation: out[j][i][k] (skip on diagonal tiles)
    if (ti != tj) {
#pragma unroll
        for (int p = 0; p < 2; p++) {
            int task = tid + p * 256;
            int cc = task & 31, rp = task >> 5; // cc: j-row, rp: i-pair
            int jj = j0 + cc, i = i0 + 2 * rp;
            if (jj < OUTN) {
                float4 v = make_float4(Ds[(2 * rp) * 33 + cc] + b0,
                                       Ds[(2 * rp + 32) * 33 + cc] + b1,
                                       Ds[(2 * rp + 1) * 33 + cc] + b0,
                                       Ds[(2 * rp + 33) * 33 + cc] + b1);
                *(float4*)&out[((size_t)jj * OUTN + i) * 2] = v;
            }
        }
    }
}

extern "C" void kernel_launch(void* const* d_in, const int* in_sizes, int n_in,
                              void* d_out, int out_size) {
    const float* x = (const float*)d_in[0];   // (1,512,1280) fp32
    const float* W = (const float*)d_in[1];   // (2560,2) fp32
    const float* b = (const float*)d_in[2];   // (2,) fp32
    float* out = (float*)d_out;               // (1,510,510,2) fp32

    prep_kernel<<<640, 256>>>(x, W);

    cudaFuncSetAttribute(pcm_mma_kernel,
                         cudaFuncAttributeMaxDynamicSharedMemorySize, SMEM_REQ);

    dim3 grid(NTRI, SPLITS);
    pcm_mma_kernel<<<grid, 256, SMEM_REQ>>>();
    pcm_reduce_kernel<<<NTRI, 256>>>(out, b);
}